// round 16
// baseline (speedup 1.0000x reference)
#include <cuda_runtime.h>
#include <math.h>

#define N_PTS 8192
#define S_PTS 4096
#define KNN   16
#define FULLM 0xffffffffu
#define NBX   64
#define NBY   64
#define NCELL (NBX * NBY)
#define XMIN_F (-8.0f)
#define XRANGE 16.0f
#define CW    (XRANGE / NBX)   // 0.25 cell width

// ---------------- scratch (__device__ globals; zero-initialized at load) ----------------
__device__ float4 g_pts[N_PTS];          // x,y,z,sq original points
__device__ float4 g_pts_s[S_PTS];        // x,y,z,sq sampled points
__device__ float4 g_spts_b[N_PTS];       // cell-sorted before points (x-major, y minor)
__device__ int    g_sidx_b[N_PTS];
__device__ float4 g_spts_a[S_PTS];       // cell-sorted after points
__device__ int    g_sidx_a[S_PTS];
__device__ int    g_cnt_b[NCELL], g_fill_b[NCELL], g_off_b[NCELL + 1];
__device__ int    g_cnt_a[NCELL], g_fill_a[NCELL], g_off_a[NCELL + 1];
__device__ int    g_ni_after[S_PTS * KNN];
__device__ int4   g_anch_a[S_PTS];       // first 4 after-neighbors (sampled idx)
__device__ int4   g_anch_b[S_PTS];       // first 4 before-neighbors (global idx)
__device__ float  g_intra_a8[S_PTS * 8]; // 6 intra dists, padded to 8
__device__ float  g_intra_b8[S_PTS * 8];
__device__ float  g_adf[S_PTS * 28];     // row-major (for gemm2 broadcast reads)
__device__ float  g_adfT[28 * S_PTS];    // transposed (for fused gemm1/statspw1 coalesced reads)
__device__ float  g_fmT[64 * S_PTS];     // transposed: [ch][s]
__device__ float  g_z[S_PTS * 128];

// ---------------- reference-rounding helpers ----------------
__device__ __forceinline__ float sq_ref(float x, float y, float z) {
    return __fadd_rn(__fadd_rn(__fmul_rn(x, x), __fmul_rn(y, y)), __fmul_rn(z, z));
}
// dot: cuBLAS SGEMM K=3 fma chain, acc0 = rn(x*x'); d2: rn elementwise fusion
__device__ __forceinline__ float d2_ref(float4 a, float4 b) {
    float dot = fmaf(a.z, b.z, fmaf(a.y, b.y, __fmul_rn(a.x, b.x)));
    float d2  = __fsub_rn(__fadd_rn(a.w, b.w), __fmul_rn(2.0f, dot));
    return fmaxf(d2, 0.0f);
}
__device__ __forceinline__ float d_ref(float4 a, float4 b) {
    float d2 = d2_ref(a, b);
    return d2 > 0.0f ? __fsqrt_rn(d2) : 0.0f;
}
__device__ __forceinline__ float leaky(float v) {
    return v >= 0.0f ? v : 0.2f * v;
}
__device__ __forceinline__ unsigned long long mk_key(float d, unsigned idx) {
    return ((unsigned long long)__float_as_uint(d) << 13) | idx;
}
__device__ __forceinline__ unsigned long long kmin64(unsigned long long a, unsigned long long b) {
    return a < b ? a : b;
}
__device__ __forceinline__ unsigned long long kmax64(unsigned long long a, unsigned long long b) {
    return a > b ? a : b;
}
__device__ __forceinline__ int cpos(float v) {   // cell coordinate in either dim
    int b = (int)((v - XMIN_F) * (NBX / XRANGE));
    return min(max(b, 0), NBX - 1);
}
__device__ __forceinline__ int cell_of(float x, float y) {
    return cpos(x) * NBY + cpos(y);
}
__device__ __forceinline__ unsigned long long bitonic32(unsigned long long key, int lane) {
#pragma unroll
    for (int k = 2; k <= 32; k <<= 1) {
#pragma unroll
        for (int j = k >> 1; j > 0; j >>= 1) {
            unsigned long long other = __shfl_xor_sync(FULLM, key, j);
            bool takemin = (((lane & k) == 0) == ((lane & j) == 0));
            key = takemin ? kmin64(key, other) : kmax64(key, other);
        }
    }
    return key;
}

// ---------------- prep + 2D hist ----------------
// g_cnt_* are zero at entry (load-time zero for call 0; scan re-zeroes for later calls).
__global__ void prep_kernel(const float* __restrict__ xyz,
                            const int* __restrict__ si,
                            float* __restrict__ out_xyz_s) {
    int i = blockIdx.x * blockDim.x + threadIdx.x;
    if (i < N_PTS) {
        float x = xyz[3 * i], y = xyz[3 * i + 1], z = xyz[3 * i + 2];
        g_pts[i] = make_float4(x, y, z, sq_ref(x, y, z));
        atomicAdd(&g_cnt_b[cell_of(x, y)], 1);
    }
    if (i < S_PTS) {
        int g = si[i];
        float x = xyz[3 * g], y = xyz[3 * g + 1], z = xyz[3 * g + 2];
        g_pts_s[i] = make_float4(x, y, z, sq_ref(x, y, z));
        out_xyz_s[3 * i]     = x;
        out_xyz_s[3 * i + 1] = y;
        out_xyz_s[3 * i + 2] = z;
        atomicAdd(&g_cnt_a[cell_of(x, y)], 1);
    }
}

// ---------------- scan: warp-shuffle prefix sums over 4096 cells + self-rezero ----------------
__device__ __forceinline__ void scan_pass(int* __restrict__ cnt, int* __restrict__ fill,
                                          int* __restrict__ off, int* __restrict__ wsum,
                                          int t, int lane, int wid) {
    int4 c = *(const int4*)(cnt + t * 4);
    int sum4 = c.x + c.y + c.z + c.w;
    int inc = sum4;
#pragma unroll
    for (int o = 1; o < 32; o <<= 1) {
        int n = __shfl_up_sync(FULLM, inc, o);
        if (lane >= o) inc += n;
    }
    if (lane == 31) wsum[wid] = inc;
    __syncthreads();
    if (t < 32) {
        int v = wsum[t];
        int iv = v;
#pragma unroll
        for (int o = 1; o < 32; o <<= 1) {
            int n = __shfl_up_sync(FULLM, iv, o);
            if (t >= o) iv += n;
        }
        wsum[t] = iv - v;                 // exclusive warp offset
    }
    __syncthreads();
    int run = wsum[wid] + inc - sum4;     // exclusive prefix for this thread's 4 cells
    off[t * 4]     = run; run += c.x;
    off[t * 4 + 1] = run; run += c.y;
    off[t * 4 + 2] = run; run += c.z;
    off[t * 4 + 3] = run; run += c.w;
    if (t == 1023) off[NCELL] = run;
    int4 z = make_int4(0, 0, 0, 0);
    *(int4*)(cnt + t * 4)  = z;           // re-zero for next call's prep
    *(int4*)(fill + t * 4) = z;           // zero for this call's scatter
}

__global__ void __launch_bounds__(1024) scan_kernel() {
    __shared__ int wsum[32];
    int t = threadIdx.x, lane = t & 31, wid = t >> 5;
    scan_pass(g_cnt_b, g_fill_b, g_off_b, wsum, t, lane, wid);
    __syncthreads();
    scan_pass(g_cnt_a, g_fill_a, g_off_a, wsum, t, lane, wid);
}

// ---------------- scatter ----------------
__global__ void scatter_kernel() {
    int i = blockIdx.x * 256 + threadIdx.x;
    if (i < N_PTS) {
        int c = cell_of(g_pts[i].x, g_pts[i].y);
        int pos = g_off_b[c] + atomicAdd(&g_fill_b[c], 1);
        g_spts_b[pos] = g_pts[i];
        g_sidx_b[pos] = i;
    } else {
        int j = i - N_PTS;
        int c = cell_of(g_pts_s[j].x, g_pts_s[j].y);
        int pos = g_off_a[c] + atomicAdd(&g_fill_a[c], 1);
        g_spts_a[pos] = g_pts_s[j];
        g_sidx_a[pos] = j;
    }
}

// ---------------- KNN core: lane-distributed sorted top-K ----------------
// key = (f32bits(d) << 13) | idx : integer order == lex (d, idx), tie -> lower index,
// exactly jax.lax.top_k(-D). Order-independent total comparator => scan order exact.
template <int K>
__device__ __forceinline__ void thr_from_key(unsigned long long key, float& thr) {
    unsigned long long kth = __shfl_sync(FULLM, key, K - 1);
    if (kth != ~0ull) {
        float dk = __uint_as_float((unsigned)(kth >> 13));
        thr = fmaf(dk, dk, 1e-3f);            // conservative fma-domain superset
    }
}

template <int K>
__device__ __forceinline__ void insert_surv(unsigned bal, unsigned long long nk,
                                            unsigned long long& key, float& thr, int lane) {
    if (!bal) return;
    do {
        int pl = __ffs(bal) - 1;
        bal &= bal - 1;
        unsigned long long ck = __shfl_sync(FULLM, nk, pl);
        unsigned lt = __ballot_sync(FULLM, ck < key);
        int pos = __ffs(lt) - 1;              // uniform across warp
        if (pos >= 0 && pos < K) {
            unsigned long long up = __shfl_up_sync(FULLM, key, 1);
            if (lane == pos)      key = ck;
            else if (lane > pos)  key = up;
            if (lane >= K)        key = ~0ull;
        }
    } while (bal);
    thr_from_key<K>(key, thr);
}

template <int K>
__device__ __forceinline__ void scan_range(int s, int e, float4 qp,
                                           const float4* __restrict__ spts,
                                           const int* __restrict__ sidx, int lane,
                                           unsigned long long& key, float& thr) {
    for (int t = s; t < e; t += 32) {
        int j = t + lane;
        bool in = j < e;
        float4 cp = in ? spts[j] : make_float4(1e30f, 1e30f, 1e30f, 1e30f);
        float dot = fmaf(qp.z, cp.z, fmaf(qp.y, cp.y, qp.x * cp.x));
        float d2f = fmaf(-2.0f, dot, qp.w + cp.w);
        bool surv = in && (d2f < thr);
        unsigned long long nk = ~0ull;
        if (surv) nk = mk_key(d_ref(qp, cp), (unsigned)sidx[j]);  // exact math on survivors
        unsigned bal = __ballot_sync(FULLM, surv);
        insert_surv<K>(bal, nk, key, thr, lane);
    }
}

template <int K, bool AFTER>
__device__ __forceinline__ void emit_knn(unsigned long long key, int q, int lane,
                                         const float4* __restrict__ cand,
                                         float* __restrict__ out_ni_f) {
    int idx = (int)(key & 0x1FFFu);
    if (AFTER && lane < K) {
        g_ni_after[q * KNN + lane] = idx;
        out_ni_f[q * KNN + lane]   = (float)idx;
    }
    unsigned long long k1 = __shfl_sync(FULLM, key, 1);
    unsigned long long k2 = __shfl_sync(FULLM, key, 2);
    unsigned long long k3 = __shfl_sync(FULLM, key, 3);
    if (lane == 0) {
        int i1 = (int)(k1 & 0x1FFF), i2 = (int)(k2 & 0x1FFF), i3 = (int)(k3 & 0x1FFF);
        float d1  = __uint_as_float((unsigned)(k1 >> 13));
        float d2v = __uint_as_float((unsigned)(k2 >> 13));
        float d3  = __uint_as_float((unsigned)(k3 >> 13));
        float4 A1 = cand[i1], A2 = cand[i2], A3 = cand[i3];
        float* intra = AFTER ? (g_intra_a8 + q * 8) : (g_intra_b8 + q * 8);
        *(float4*)intra       = make_float4(d1, d2v, d3, d_ref(A1, A2));
        *(float4*)(intra + 4) = make_float4(d_ref(A1, A3), d_ref(A2, A3), 0.0f, 0.0f);
        if (AFTER) g_anch_a[q] = make_int4(idx, i1, i2, i3);
        else       g_anch_b[q] = make_int4(idx, i1, i2, i3);
    }
}

// warp-per-query 2D cell sweep. Row-major cells (x-major) => each x-column's y-window
// is one contiguous range. Pruning: a skipped candidate has
// d_exact >= sqrt(dx_edge^2 + dy^2) > sqrt(thr) >= d_K (1e-3 slack covers fp rounding,
// ties included since thr > d_K^2 strictly). Seed range is excluded from the rescan.
template <int K, bool AFTER>
__device__ __forceinline__ void knn_cell_warp(int p, int lane, float* __restrict__ out_ni_f) {
    const float4* __restrict__ spts = AFTER ? g_spts_a : g_spts_b;
    const int*   __restrict__ sidx  = AFTER ? g_sidx_a : g_sidx_b;
    const int*   __restrict__ off   = AFTER ? g_off_a  : g_off_b;
    const float4* __restrict__ cand = AFTER ? g_pts_s  : g_pts;

    float4 qp = g_spts_a[p];          // queries: sampled points in cell-sorted order
    int q = g_sidx_a[p];
    float qx = qp.x, qy = qp.y;

    int qbx = cpos(qx);
    int coff = qbx * NBY;
    int colA = off[coff], colB = off[coff + NBY];

    // seed: up to 32 candidates centered on the query's y-cell within own column
    int sstart = off[coff + cpos(qy)] - 16;
    sstart = min(max(sstart, colA), max(colA, colB - 32));
    int send = min(colB, sstart + 32);

    int j = sstart + lane;
    bool v = j < send;
    float4 c0 = v ? spts[j] : make_float4(1e30f, 1e30f, 1e30f, 1e30f);
    unsigned long long key = v ? mk_key(d_ref(qp, c0), (unsigned)sidx[j]) : ~0ull;
    key = bitonic32(key, lane);
    if (lane >= K) key = ~0ull;
    float thr = 3.4e38f;
    thr_from_key<K>(key, thr);

    // own column: y-window minus the seeded subrange
    {
        float ry = sqrtf(thr);
        int cy0 = cpos(qy - ry - 1e-3f), cy1 = cpos(qy + ry + 1e-3f);
        int a = off[coff + cy0], b = off[coff + cy1 + 1];
        scan_range<K>(a, min(b, sstart), qp, spts, sidx, lane, key, thr);
        scan_range<K>(max(a, send), b, qp, spts, sidx, lane, key, thr);
    }

    // expand x-columns outward, nearer side first
    int bl = qbx - 1, br = qbx + 1;
    while (true) {
        float dl = 1e30f, dr = 1e30f;
        if (bl >= 0)  dl = fmaxf(0.0f, qx - (XMIN_F + (bl + 1) * CW) - 1e-3f);
        if (br < NBX) dr = fmaxf(0.0f, (XMIN_F + br * CW) - qx - 1e-3f);
        bool okl = (bl >= 0)  && (dl * dl < thr);
        bool okr = (br < NBX) && (dr * dr < thr);
        if (!okl && !okr) break;
        int c; float dx;
        if (okl && (!okr || dl <= dr)) { c = bl; dx = dl; bl--; }
        else                           { c = br; dx = dr; br++; }
        float ry = sqrtf(fmaxf(thr - dx * dx, 0.0f));
        int cf = c * NBY;
        int cy0 = cpos(qy - ry - 1e-3f), cy1 = cpos(qy + ry + 1e-3f);
        scan_range<K>(off[cf + cy0], off[cf + cy1 + 1], qp, spts, sidx, lane, key, thr);
    }
    emit_knn<K, AFTER>(key, q, lane, cand, out_ni_f);
}

__global__ void __launch_bounds__(256) knn_kernel(float* __restrict__ out_ni_f) {
    int gw   = blockIdx.x * 8 + (threadIdx.x >> 5);   // 8192 warps
    int lane = threadIdx.x & 31;
    if (gw < S_PTS) knn_cell_warp<KNN, true >(gw, lane, out_ni_f);
    else            knn_cell_warp<4,   false>(gw - S_PTS, lane, out_ni_f);
}

// ---------------- fused rf (1024 blocks, 4 threads/row) + adf (16 blocks) ----------------
// adf branch also writes adfT[c][s] (coalesced across s) for the fused statspw1.
__global__ void __launch_bounds__(256) rf_adf_kernel(float* __restrict__ out_rf,
                                                     const int* __restrict__ si) {
    int b = blockIdx.x;
    if (b < 1024) {
        int id = b * 256 + threadIdx.x;           // < 262144
        int i = id >> 2, h = id & 3;              // row, quarter
        int n = i >> 4, k = i & 15;
        int nb = g_ni_after[n * KNN + k];
        int4 an  = g_anch_a[n];
        int4 anb = g_anch_a[nb];
        float4 Q0 = g_pts_s[anb.x], Q1 = g_pts_s[anb.y], Q2 = g_pts_s[anb.z], Q3 = g_pts_s[anb.w];
        float* o = out_rf + (size_t)i * 28;
        float4 P;
        if (h == 0) {
            float4 a0 = *(const float4*)(g_intra_a8 + n * 8);
            float4 a1 = *(const float4*)(g_intra_a8 + n * 8 + 4);
            float4 c0 = *(const float4*)(g_intra_a8 + nb * 8);
            float4 c1 = *(const float4*)(g_intra_a8 + nb * 8 + 4);
            ((float4*)o)[0] = make_float4(a0.x, a0.y, a0.z, a0.w);
            ((float4*)o)[1] = make_float4(a1.x, a1.y, c0.x, c0.y);
            ((float4*)o)[2] = make_float4(c0.z, c0.w, c1.x, c1.y);
            P = g_pts_s[an.x];
        } else if (h == 1) P = g_pts_s[an.y];
        else if (h == 2)   P = g_pts_s[an.z];
        else               P = g_pts_s[an.w];
        ((float4*)o)[3 + h] = make_float4(d_ref(P,Q0), d_ref(P,Q1), d_ref(P,Q2), d_ref(P,Q3));
    } else {
        int s = (b - 1024) * 256 + threadIdx.x;   // < 4096
        float4 b0 = *(const float4*)(g_intra_b8 + s * 8);
        float4 b1 = *(const float4*)(g_intra_b8 + s * 8 + 4);
        float4 a0 = *(const float4*)(g_intra_a8 + s * 8);
        float4 a1 = *(const float4*)(g_intra_a8 + s * 8 + 4);
        int4 ab = g_anch_b[s];
        int4 aa = g_anch_a[s];
        float4 P0 = g_pts[ab.x], P1 = g_pts[ab.y], P2 = g_pts[ab.z], P3 = g_pts[ab.w];
        float4 Q0 = g_pts[si[aa.x]], Q1 = g_pts[si[aa.y]], Q2 = g_pts[si[aa.z]], Q3 = g_pts[si[aa.w]];
        float4 rows[7];
        rows[0] = make_float4(b0.x, b0.y, b0.z, b0.w);
        rows[1] = make_float4(b1.x, b1.y, a0.x, a0.y);
        rows[2] = make_float4(a0.z, a0.w, a1.x, a1.y);
        rows[3] = make_float4(d_ref(P0,Q0), d_ref(P0,Q1), d_ref(P0,Q2), d_ref(P0,Q3));
        rows[4] = make_float4(d_ref(P1,Q0), d_ref(P1,Q1), d_ref(P1,Q2), d_ref(P1,Q3));
        rows[5] = make_float4(d_ref(P2,Q0), d_ref(P2,Q1), d_ref(P2,Q2), d_ref(P2,Q3));
        rows[6] = make_float4(d_ref(P3,Q0), d_ref(P3,Q1), d_ref(P3,Q2), d_ref(P3,Q3));
        float* o = g_adf + s * 28;
#pragma unroll
        for (int r = 0; r < 7; r++) {
            ((float4*)o)[r] = rows[r];
            g_adfT[(r * 4    ) * S_PTS + s] = rows[r].x;
            g_adfT[(r * 4 + 1) * S_PTS + s] = rows[r].y;
            g_adfT[(r * 4 + 2) * S_PTS + s] = rows[r].z;
            g_adfT[(r * 4 + 3) * S_PTS + s] = rows[r].w;
        }
    }
}

// ---------------- statspw1: FUSED gemm1 + BN stats (w & b) + gate + leaky ----------------
// 32 blocks x 2 channels. y computed in registers from coalesced adfT columns with
// c-ascending fma chains (identical order to the former gemm1 -> bitwise-same y),
// then sums in i-ascending order (identical to previous statspw1 -> bitwise-same stats).
__global__ void __launch_bounds__(256) statspw1_kernel(
    const float* __restrict__ Ww, const float* __restrict__ bw,
    const float* __restrict__ Wb, const float* __restrict__ bb,
    const float* __restrict__ gw, const float* __restrict__ betaw,
    const float* __restrict__ gb, const float* __restrict__ betab,
    const float* __restrict__ feature, const int* __restrict__ si) {
    __shared__ float wsm[4 * 28];         // ww0 ww1 wb0 wb1 per c
    __shared__ float2 red[256], red2[256];
    __shared__ float  stats[8];
    int ch2 = blockIdx.x * 2, tid = threadIdx.x;
    if (tid < 28) {
        wsm[tid]          = Ww[tid * 64 + ch2];
        wsm[28 + tid]     = Ww[tid * 64 + ch2 + 1];
        wsm[56 + tid]     = Wb[tid * 64 + ch2];
        wsm[84 + tid]     = Wb[tid * 64 + ch2 + 1];
    }
    __syncthreads();
    float bw0 = bw[ch2], bw1 = bw[ch2 + 1], bb0 = bb[ch2], bb1 = bb[ch2 + 1];
    float2 vw[16], vb[16];
#pragma unroll
    for (int i = 0; i < 16; i++) {
        vw[i] = make_float2(bw0, bw1);
        vb[i] = make_float2(bb0, bb1);
    }
    for (int c = 0; c < 28; c++) {        // c-ascending: same chain as gemm1
        float w0 = wsm[c], w1 = wsm[28 + c], u0 = wsm[56 + c], u1 = wsm[84 + c];
        const float* col = g_adfT + (size_t)c * S_PTS;
#pragma unroll
        for (int i = 0; i < 16; i++) {
            float a = col[i * 256 + tid];  // coalesced
            vw[i].x = fmaf(a, w0, vw[i].x);
            vw[i].y = fmaf(a, w1, vw[i].y);
            vb[i].x = fmaf(a, u0, vb[i].x);
            vb[i].y = fmaf(a, u1, vb[i].y);
        }
    }
    float2 sw = make_float2(0.f, 0.f), s2w = make_float2(0.f, 0.f);
    float2 sb = make_float2(0.f, 0.f), s2b = make_float2(0.f, 0.f);
#pragma unroll
    for (int i = 0; i < 16; i++) {        // i-ascending: same sum order as before
        float2 w = vw[i], b = vb[i];
        sw.x += w.x; sw.y += w.y; s2w.x = fmaf(w.x, w.x, s2w.x); s2w.y = fmaf(w.y, w.y, s2w.y);
        sb.x += b.x; sb.y += b.y; s2b.x = fmaf(b.x, b.x, s2b.x); s2b.y = fmaf(b.y, b.y, s2b.y);
    }
    red[tid] = sw; red2[tid] = s2w; __syncthreads();
    for (int st = 128; st > 0; st >>= 1) {
        if (tid < st) {
            red[tid].x += red[tid + st].x;  red[tid].y += red[tid + st].y;
            red2[tid].x += red2[tid + st].x; red2[tid].y += red2[tid + st].y;
        }
        __syncthreads();
    }
    if (tid == 0) {
        float mu0 = red[0].x / (float)S_PTS, mu1 = red[0].y / (float)S_PTS;
        stats[0] = mu0; stats[1] = mu1;
        stats[2] = rsqrtf(red2[0].x / (float)S_PTS - mu0 * mu0 + 1e-5f);
        stats[3] = rsqrtf(red2[0].y / (float)S_PTS - mu1 * mu1 + 1e-5f);
    }
    __syncthreads();
    red[tid] = sb; red2[tid] = s2b; __syncthreads();
    for (int st = 128; st > 0; st >>= 1) {
        if (tid < st) {
            red[tid].x += red[tid + st].x;  red[tid].y += red[tid + st].y;
            red2[tid].x += red2[tid + st].x; red2[tid].y += red2[tid + st].y;
        }
        __syncthreads();
    }
    if (tid == 0) {
        float mu0 = red[0].x / (float)S_PTS, mu1 = red[0].y / (float)S_PTS;
        stats[4] = mu0; stats[5] = mu1;
        stats[6] = rsqrtf(red2[0].x / (float)S_PTS - mu0 * mu0 + 1e-5f);
        stats[7] = rsqrtf(red2[0].y / (float)S_PTS - mu1 * mu1 + 1e-5f);
    }
    __syncthreads();
    float muw0 = stats[0], muw1 = stats[1], rsw0 = stats[2], rsw1 = stats[3];
    float mub0 = stats[4], mub1 = stats[5], rsb0 = stats[6], rsb1 = stats[7];
    float gw0 = gw[ch2], gw1 = gw[ch2 + 1], bew0 = betaw[ch2], bew1 = betaw[ch2 + 1];
    float gb0 = gb[ch2], gb1 = gb[ch2 + 1], beb0 = betab[ch2], beb1 = betab[ch2 + 1];
#pragma unroll
    for (int i = 0; i < 16; i++) {
        int r = i * 256 + tid;
        float2 f = *(const float2*)(feature + (size_t)si[r] * 64 + ch2);
        float w0 = (vw[i].x - muw0) * rsw0 * gw0 + bew0;
        float w1 = (vw[i].y - muw1) * rsw1 * gw1 + bew1;
        float b0 = (vb[i].x - mub0) * rsb0 * gb0 + beb0;
        float b1 = (vb[i].y - mub1) * rsb1 * gb1 + beb1;
        g_fmT[(size_t)ch2 * S_PTS + r]       = leaky(fmaf(f.x, w0, b0));
        g_fmT[(size_t)(ch2 + 1) * S_PTS + r] = leaky(fmaf(f.y, w1, b1));
    }
}

// ---------------- GEMM2: z = [fm | adf] @ Wo + bo, 2 channels/thread, float2 Wo ----------------
// fma order per channel identical to the 1-ch version -> bitwise-identical z.
__global__ void __launch_bounds__(256) gemm2_kernel(const float* __restrict__ Wo,
                                                    const float* __restrict__ bo) {
    int tid = blockIdx.x * blockDim.x + threadIdx.x;    // < S_PTS*64
    int ch = (tid & 63) * 2, s = tid >> 6;
    float2 acc = *(const float2*)(bo + ch);
#pragma unroll
    for (int c = 0; c < 64; c++) {
        float f = g_fmT[c * S_PTS + s];
        float2 w = *(const float2*)(Wo + c * 128 + ch);
        acc.x = fmaf(f, w.x, acc.x);
        acc.y = fmaf(f, w.y, acc.y);
    }
    const float* a = g_adf + s * 28;
#pragma unroll
    for (int c = 0; c < 28; c++) {
        float av = a[c];
        float2 w = *(const float2*)(Wo + (64 + c) * 128 + ch);
        acc.x = fmaf(av, w.x, acc.x);
        acc.y = fmaf(av, w.y, acc.y);
    }
    *(float2*)(g_z + (size_t)s * 128 + ch) = acc;
}

// ---------------- bnpw2: BN stats + affine + leaky, 4 channels/block, float4 I/O ----------------
__global__ void __launch_bounds__(256) bnpw2_kernel(const float* __restrict__ go,
                                                    const float* __restrict__ betao,
                                                    float* __restrict__ out_feat) {
    __shared__ float4 red[256], red2[256];
    __shared__ float4 stats[2];
    int ch4 = blockIdx.x * 4, tid = threadIdx.x;
    float4 v[16];
    float4 s  = make_float4(0.f, 0.f, 0.f, 0.f);
    float4 s2 = make_float4(0.f, 0.f, 0.f, 0.f);
#pragma unroll
    for (int i = 0; i < 16; i++) {
        int r = i * 256 + tid;
        float4 val = *(const float4*)(g_z + (size_t)r * 128 + ch4);
        v[i] = val;
        s.x += val.x; s.y += val.y; s.z += val.z; s.w += val.w;
        s2.x = fmaf(val.x, val.x, s2.x); s2.y = fmaf(val.y, val.y, s2.y);
        s2.z = fmaf(val.z, val.z, s2.z); s2.w = fmaf(val.w, val.w, s2.w);
    }
    red[tid] = s; red2[tid] = s2;
    __syncthreads();
    for (int st = 128; st > 0; st >>= 1) {
        if (tid < st) {
            float4 a = red[tid + st], a2 = red2[tid + st];
            red[tid].x += a.x; red[tid].y += a.y; red[tid].z += a.z; red[tid].w += a.w;
            red2[tid].x += a2.x; red2[tid].y += a2.y; red2[tid].z += a2.z; red2[tid].w += a2.w;
        }
        __syncthreads();
    }
    if (tid == 0) {
        float4 sum = red[0], sum2 = red2[0];
        float4 mu = make_float4(sum.x / S_PTS, sum.y / S_PTS, sum.z / S_PTS, sum.w / S_PTS);
        stats[0] = mu;
        stats[1] = make_float4(rsqrtf(sum2.x / S_PTS - mu.x * mu.x + 1e-5f),
                               rsqrtf(sum2.y / S_PTS - mu.y * mu.y + 1e-5f),
                               rsqrtf(sum2.z / S_PTS - mu.z * mu.z + 1e-5f),
                               rsqrtf(sum2.w / S_PTS - mu.w * mu.w + 1e-5f));
    }
    __syncthreads();
    float4 mu = stats[0], rs = stats[1];
    float4 g  = *(const float4*)(go + ch4);
    float4 be = *(const float4*)(betao + ch4);
#pragma unroll
    for (int i = 0; i < 16; i++) {
        int r = i * 256 + tid;
        float4 val = v[i];
        float4 o;
        o.x = leaky((val.x - mu.x) * rs.x * g.x + be.x);
        o.y = leaky((val.y - mu.y) * rs.y * g.y + be.y);
        o.z = leaky((val.z - mu.z) * rs.z * g.z + be.z);
        o.w = leaky((val.w - mu.w) * rs.w * g.w + be.w);
        *(float4*)(out_feat + (size_t)r * 128 + ch4) = o;
    }
}

// ---------------- launch ----------------
extern "C" void kernel_launch(void* const* d_in, const int* in_sizes, int n_in,
                              void* d_out, int out_size) {
    const float* xyz     = (const float*)d_in[0];
    const float* feature = (const float*)d_in[1];
    const int*   si      = (const int*)  d_in[2];
    const float* Ww    = (const float*)d_in[3];
    const float* bw    = (const float*)d_in[4];
    const float* gw    = (const float*)d_in[5];
    const float* betaw = (const float*)d_in[6];
    const float* Wb    = (const float*)d_in[7];
    const float* bb    = (const float*)d_in[8];
    const float* gb    = (const float*)d_in[9];
    const float* betab = (const float*)d_in[10];
    const float* Wo    = (const float*)d_in[11];
    const float* bo    = (const float*)d_in[12];
    const float* go    = (const float*)d_in[13];
    const float* betao = (const float*)d_in[14];

    float* out        = (float*)d_out;
    float* out_xyz_s  = out;                                  // 4096*3
    float* out_feat   = out + S_PTS * 3;                      // 4096*128
    float* out_rf     = out_feat + S_PTS * 128;               // 4096*16*28
    float* out_ni     = out_rf + (size_t)S_PTS * KNN * 28;    // 4096*16

    prep_kernel<<<(N_PTS + 255) / 256, 256>>>(xyz, si, out_xyz_s);
    scan_kernel<<<1, 1024>>>();
    scatter_kernel<<<(N_PTS + S_PTS) / 256, 256>>>();
    knn_kernel<<<1024, 256>>>(out_ni);                         // 8192 warps
    rf_adf_kernel<<<1040, 256>>>(out_rf, si);
    statspw1_kernel<<<32, 256>>>(Ww, bw, Wb, bb, gw, betaw, gb, betab, feature, si);
    gemm2_kernel<<<(S_PTS * 64) / 256, 256>>>(Wo, bo);
    bnpw2_kernel<<<32, 256>>>(go, betao, out_feat);
}

// round 17
// speedup vs baseline: 1.2597x; 1.2597x over previous
#include <cuda_runtime.h>
#include <math.h>

#define N_PTS 8192
#define S_PTS 4096
#define KNN   16
#define FULLM 0xffffffffu
#define NBX   64
#define NBY   64
#define NCELL (NBX * NBY)
#define XMIN_F (-8.0f)
#define XRANGE 16.0f
#define CW    (XRANGE / NBX)   // 0.25 cell width

// ---------------- scratch (__device__ globals; zero-initialized at load) ----------------
__device__ float4 g_pts[N_PTS];          // x,y,z,sq original points
__device__ float4 g_pts_s[S_PTS];        // x,y,z,sq sampled points
__device__ float4 g_spts_b[N_PTS];       // cell-sorted before points (x-major, y minor)
__device__ int    g_sidx_b[N_PTS];
__device__ float4 g_spts_a[S_PTS];       // cell-sorted after points
__device__ int    g_sidx_a[S_PTS];
__device__ int    g_cnt_b[NCELL], g_fill_b[NCELL], g_off_b[NCELL + 1];
__device__ int    g_cnt_a[NCELL], g_fill_a[NCELL], g_off_a[NCELL + 1];
__device__ int    g_ni_after[S_PTS * KNN];
__device__ int4   g_anch_a[S_PTS];       // first 4 after-neighbors (sampled idx)
__device__ int4   g_anch_b[S_PTS];       // first 4 before-neighbors (global idx)
__device__ float  g_intra_a8[S_PTS * 8]; // 6 intra dists, padded to 8
__device__ float  g_intra_b8[S_PTS * 8];
__device__ float  g_adf[S_PTS * 28];
__device__ float  g_y[S_PTS * 128];      // [s][0:64)=yw, [s][64:128)=yb
__device__ float  g_fmT[64 * S_PTS];     // transposed: [ch][s]
__device__ float  g_z[S_PTS * 128];

// ---------------- reference-rounding helpers ----------------
__device__ __forceinline__ float sq_ref(float x, float y, float z) {
    return __fadd_rn(__fadd_rn(__fmul_rn(x, x), __fmul_rn(y, y)), __fmul_rn(z, z));
}
// dot: cuBLAS SGEMM K=3 fma chain, acc0 = rn(x*x'); d2: rn elementwise fusion
__device__ __forceinline__ float d2_ref(float4 a, float4 b) {
    float dot = fmaf(a.z, b.z, fmaf(a.y, b.y, __fmul_rn(a.x, b.x)));
    float d2  = __fsub_rn(__fadd_rn(a.w, b.w), __fmul_rn(2.0f, dot));
    return fmaxf(d2, 0.0f);
}
__device__ __forceinline__ float d_ref(float4 a, float4 b) {
    float d2 = d2_ref(a, b);
    return d2 > 0.0f ? __fsqrt_rn(d2) : 0.0f;
}
__device__ __forceinline__ float leaky(float v) {
    return v >= 0.0f ? v : 0.2f * v;
}
__device__ __forceinline__ unsigned long long mk_key(float d, unsigned idx) {
    return ((unsigned long long)__float_as_uint(d) << 13) | idx;
}
__device__ __forceinline__ unsigned long long kmin64(unsigned long long a, unsigned long long b) {
    return a < b ? a : b;
}
__device__ __forceinline__ unsigned long long kmax64(unsigned long long a, unsigned long long b) {
    return a > b ? a : b;
}
__device__ __forceinline__ int cpos(float v) {   // cell coordinate in either dim
    int b = (int)((v - XMIN_F) * (NBX / XRANGE));
    return min(max(b, 0), NBX - 1);
}
__device__ __forceinline__ int cell_of(float x, float y) {
    return cpos(x) * NBY + cpos(y);
}
__device__ __forceinline__ unsigned long long bitonic32(unsigned long long key, int lane) {
#pragma unroll
    for (int k = 2; k <= 32; k <<= 1) {
#pragma unroll
        for (int j = k >> 1; j > 0; j >>= 1) {
            unsigned long long other = __shfl_xor_sync(FULLM, key, j);
            bool takemin = (((lane & k) == 0) == ((lane & j) == 0));
            key = takemin ? kmin64(key, other) : kmax64(key, other);
        }
    }
    return key;
}

// ---------------- prep + 2D hist ----------------
// g_cnt_* are zero at entry (load-time zero for call 0; scan re-zeroes for later calls).
__global__ void prep_kernel(const float* __restrict__ xyz,
                            const int* __restrict__ si,
                            float* __restrict__ out_xyz_s) {
    int i = blockIdx.x * blockDim.x + threadIdx.x;
    if (i < N_PTS) {
        float x = xyz[3 * i], y = xyz[3 * i + 1], z = xyz[3 * i + 2];
        g_pts[i] = make_float4(x, y, z, sq_ref(x, y, z));
        atomicAdd(&g_cnt_b[cell_of(x, y)], 1);
    }
    if (i < S_PTS) {
        int g = si[i];
        float x = xyz[3 * g], y = xyz[3 * g + 1], z = xyz[3 * g + 2];
        g_pts_s[i] = make_float4(x, y, z, sq_ref(x, y, z));
        out_xyz_s[3 * i]     = x;
        out_xyz_s[3 * i + 1] = y;
        out_xyz_s[3 * i + 2] = z;
        atomicAdd(&g_cnt_a[cell_of(x, y)], 1);
    }
}

// ---------------- scan: warp-shuffle prefix sums over 4096 cells + self-rezero ----------------
__device__ __forceinline__ void scan_pass(int* __restrict__ cnt, int* __restrict__ fill,
                                          int* __restrict__ off, int* __restrict__ wsum,
                                          int t, int lane, int wid) {
    int4 c = *(const int4*)(cnt + t * 4);
    int sum4 = c.x + c.y + c.z + c.w;
    int inc = sum4;
#pragma unroll
    for (int o = 1; o < 32; o <<= 1) {
        int n = __shfl_up_sync(FULLM, inc, o);
        if (lane >= o) inc += n;
    }
    if (lane == 31) wsum[wid] = inc;
    __syncthreads();
    if (t < 32) {
        int v = wsum[t];
        int iv = v;
#pragma unroll
        for (int o = 1; o < 32; o <<= 1) {
            int n = __shfl_up_sync(FULLM, iv, o);
            if (t >= o) iv += n;
        }
        wsum[t] = iv - v;                 // exclusive warp offset
    }
    __syncthreads();
    int run = wsum[wid] + inc - sum4;     // exclusive prefix for this thread's 4 cells
    off[t * 4]     = run; run += c.x;
    off[t * 4 + 1] = run; run += c.y;
    off[t * 4 + 2] = run; run += c.z;
    off[t * 4 + 3] = run; run += c.w;
    if (t == 1023) off[NCELL] = run;
    int4 z = make_int4(0, 0, 0, 0);
    *(int4*)(cnt + t * 4)  = z;           // re-zero for next call's prep
    *(int4*)(fill + t * 4) = z;           // zero for this call's scatter
}

__global__ void __launch_bounds__(1024) scan_kernel() {
    __shared__ int wsum[32];
    int t = threadIdx.x, lane = t & 31, wid = t >> 5;
    scan_pass(g_cnt_b, g_fill_b, g_off_b, wsum, t, lane, wid);
    __syncthreads();
    scan_pass(g_cnt_a, g_fill_a, g_off_a, wsum, t, lane, wid);
}

// ---------------- scatter ----------------
__global__ void scatter_kernel() {
    int i = blockIdx.x * 256 + threadIdx.x;
    if (i < N_PTS) {
        int c = cell_of(g_pts[i].x, g_pts[i].y);
        int pos = g_off_b[c] + atomicAdd(&g_fill_b[c], 1);
        g_spts_b[pos] = g_pts[i];
        g_sidx_b[pos] = i;
    } else {
        int j = i - N_PTS;
        int c = cell_of(g_pts_s[j].x, g_pts_s[j].y);
        int pos = g_off_a[c] + atomicAdd(&g_fill_a[c], 1);
        g_spts_a[pos] = g_pts_s[j];
        g_sidx_a[pos] = j;
    }
}

// ---------------- KNN core: lane-distributed sorted top-K ----------------
// key = (f32bits(d) << 13) | idx : integer order == lex (d, idx), tie -> lower index,
// exactly jax.lax.top_k(-D). Order-independent total comparator => scan order exact.
template <int K>
__device__ __forceinline__ void thr_from_key(unsigned long long key, float& thr) {
    unsigned long long kth = __shfl_sync(FULLM, key, K - 1);
    if (kth != ~0ull) {
        float dk = __uint_as_float((unsigned)(kth >> 13));
        thr = fmaf(dk, dk, 1e-3f);            // conservative fma-domain superset
    }
}

template <int K>
__device__ __forceinline__ void insert_surv(unsigned bal, unsigned long long nk,
                                            unsigned long long& key, float& thr, int lane) {
    if (!bal) return;
    do {
        int pl = __ffs(bal) - 1;
        bal &= bal - 1;
        unsigned long long ck = __shfl_sync(FULLM, nk, pl);
        unsigned lt = __ballot_sync(FULLM, ck < key);
        int pos = __ffs(lt) - 1;              // uniform across warp
        if (pos >= 0 && pos < K) {
            unsigned long long up = __shfl_up_sync(FULLM, key, 1);
            if (lane == pos)      key = ck;
            else if (lane > pos)  key = up;
            if (lane >= K)        key = ~0ull;
        }
    } while (bal);
    thr_from_key<K>(key, thr);
}

template <int K>
__device__ __forceinline__ void scan_range(int s, int e, float4 qp,
                                           const float4* __restrict__ spts,
                                           const int* __restrict__ sidx, int lane,
                                           unsigned long long& key, float& thr) {
    for (int t = s; t < e; t += 32) {
        int j = t + lane;
        bool in = j < e;
        float4 cp = in ? spts[j] : make_float4(1e30f, 1e30f, 1e30f, 1e30f);
        float dot = fmaf(qp.z, cp.z, fmaf(qp.y, cp.y, qp.x * cp.x));
        float d2f = fmaf(-2.0f, dot, qp.w + cp.w);
        bool surv = in && (d2f < thr);
        unsigned long long nk = ~0ull;
        if (surv) nk = mk_key(d_ref(qp, cp), (unsigned)sidx[j]);  // exact math on survivors
        unsigned bal = __ballot_sync(FULLM, surv);
        insert_surv<K>(bal, nk, key, thr, lane);
    }
}

template <int K, bool AFTER>
__device__ __forceinline__ void emit_knn(unsigned long long key, int q, int lane,
                                         const float4* __restrict__ cand,
                                         float* __restrict__ out_ni_f) {
    int idx = (int)(key & 0x1FFFu);
    if (AFTER && lane < K) {
        g_ni_after[q * KNN + lane] = idx;
        out_ni_f[q * KNN + lane]   = (float)idx;
    }
    unsigned long long k1 = __shfl_sync(FULLM, key, 1);
    unsigned long long k2 = __shfl_sync(FULLM, key, 2);
    unsigned long long k3 = __shfl_sync(FULLM, key, 3);
    if (lane == 0) {
        int i1 = (int)(k1 & 0x1FFF), i2 = (int)(k2 & 0x1FFF), i3 = (int)(k3 & 0x1FFF);
        float d1  = __uint_as_float((unsigned)(k1 >> 13));
        float d2v = __uint_as_float((unsigned)(k2 >> 13));
        float d3  = __uint_as_float((unsigned)(k3 >> 13));
        float4 A1 = cand[i1], A2 = cand[i2], A3 = cand[i3];
        float* intra = AFTER ? (g_intra_a8 + q * 8) : (g_intra_b8 + q * 8);
        *(float4*)intra       = make_float4(d1, d2v, d3, d_ref(A1, A2));
        *(float4*)(intra + 4) = make_float4(d_ref(A1, A3), d_ref(A2, A3), 0.0f, 0.0f);
        if (AFTER) g_anch_a[q] = make_int4(idx, i1, i2, i3);
        else       g_anch_b[q] = make_int4(idx, i1, i2, i3);
    }
}

// warp-per-query 2D cell sweep. Row-major cells (x-major) => each x-column's y-window
// is one contiguous range. Pruning: a skipped candidate has
// d_exact >= sqrt(dx_edge^2 + dy^2) > sqrt(thr) >= d_K (1e-3 slack covers fp rounding,
// ties included since thr > d_K^2 strictly). Seed range is excluded from the rescan.
template <int K, bool AFTER>
__device__ __forceinline__ void knn_cell_warp(int p, int lane, float* __restrict__ out_ni_f) {
    const float4* __restrict__ spts = AFTER ? g_spts_a : g_spts_b;
    const int*   __restrict__ sidx  = AFTER ? g_sidx_a : g_sidx_b;
    const int*   __restrict__ off   = AFTER ? g_off_a  : g_off_b;
    const float4* __restrict__ cand = AFTER ? g_pts_s  : g_pts;

    float4 qp = g_spts_a[p];          // queries: sampled points in cell-sorted order
    int q = g_sidx_a[p];
    float qx = qp.x, qy = qp.y;

    int qbx = cpos(qx);
    int coff = qbx * NBY;
    int colA = off[coff], colB = off[coff + NBY];

    // seed: up to 32 candidates centered on the query's y-cell within own column
    int sstart = off[coff + cpos(qy)] - 16;
    sstart = min(max(sstart, colA), max(colA, colB - 32));
    int send = min(colB, sstart + 32);

    int j = sstart + lane;
    bool v = j < send;
    float4 c0 = v ? spts[j] : make_float4(1e30f, 1e30f, 1e30f, 1e30f);
    unsigned long long key = v ? mk_key(d_ref(qp, c0), (unsigned)sidx[j]) : ~0ull;
    key = bitonic32(key, lane);
    if (lane >= K) key = ~0ull;
    float thr = 3.4e38f;
    thr_from_key<K>(key, thr);

    // own column: y-window minus the seeded subrange
    {
        float ry = sqrtf(thr);
        int cy0 = cpos(qy - ry - 1e-3f), cy1 = cpos(qy + ry + 1e-3f);
        int a = off[coff + cy0], b = off[coff + cy1 + 1];
        scan_range<K>(a, min(b, sstart), qp, spts, sidx, lane, key, thr);
        scan_range<K>(max(a, send), b, qp, spts, sidx, lane, key, thr);
    }

    // expand x-columns outward, nearer side first
    int bl = qbx - 1, br = qbx + 1;
    while (true) {
        float dl = 1e30f, dr = 1e30f;
        if (bl >= 0)  dl = fmaxf(0.0f, qx - (XMIN_F + (bl + 1) * CW) - 1e-3f);
        if (br < NBX) dr = fmaxf(0.0f, (XMIN_F + br * CW) - qx - 1e-3f);
        bool okl = (bl >= 0)  && (dl * dl < thr);
        bool okr = (br < NBX) && (dr * dr < thr);
        if (!okl && !okr) break;
        int c; float dx;
        if (okl && (!okr || dl <= dr)) { c = bl; dx = dl; bl--; }
        else                           { c = br; dx = dr; br++; }
        float ry = sqrtf(fmaxf(thr - dx * dx, 0.0f));
        int cf = c * NBY;
        int cy0 = cpos(qy - ry - 1e-3f), cy1 = cpos(qy + ry + 1e-3f);
        scan_range<K>(off[cf + cy0], off[cf + cy1 + 1], qp, spts, sidx, lane, key, thr);
    }
    emit_knn<K, AFTER>(key, q, lane, cand, out_ni_f);
}

__global__ void __launch_bounds__(256) knn_kernel(float* __restrict__ out_ni_f) {
    int gw   = blockIdx.x * 8 + (threadIdx.x >> 5);   // 8192 warps
    int lane = threadIdx.x & 31;
    if (gw < S_PTS) knn_cell_warp<KNN, true >(gw, lane, out_ni_f);
    else            knn_cell_warp<4,   false>(gw - S_PTS, lane, out_ni_f);
}

// ---------------- fused rf (1024 blocks, 4 threads/row) + adf (16 blocks) ----------------
__global__ void __launch_bounds__(256) rf_adf_kernel(float* __restrict__ out_rf,
                                                     const int* __restrict__ si) {
    int b = blockIdx.x;
    if (b < 1024) {
        int id = b * 256 + threadIdx.x;           // < 262144
        int i = id >> 2, h = id & 3;              // row, quarter
        int n = i >> 4, k = i & 15;
        int nb = g_ni_after[n * KNN + k];
        int4 an  = g_anch_a[n];
        int4 anb = g_anch_a[nb];
        float4 Q0 = g_pts_s[anb.x], Q1 = g_pts_s[anb.y], Q2 = g_pts_s[anb.z], Q3 = g_pts_s[anb.w];
        float* o = out_rf + (size_t)i * 28;
        float4 P;
        if (h == 0) {
            float4 a0 = *(const float4*)(g_intra_a8 + n * 8);
            float4 a1 = *(const float4*)(g_intra_a8 + n * 8 + 4);
            float4 c0 = *(const float4*)(g_intra_a8 + nb * 8);
            float4 c1 = *(const float4*)(g_intra_a8 + nb * 8 + 4);
            ((float4*)o)[0] = make_float4(a0.x, a0.y, a0.z, a0.w);
            ((float4*)o)[1] = make_float4(a1.x, a1.y, c0.x, c0.y);
            ((float4*)o)[2] = make_float4(c0.z, c0.w, c1.x, c1.y);
            P = g_pts_s[an.x];
        } else if (h == 1) P = g_pts_s[an.y];
        else if (h == 2)   P = g_pts_s[an.z];
        else               P = g_pts_s[an.w];
        ((float4*)o)[3 + h] = make_float4(d_ref(P,Q0), d_ref(P,Q1), d_ref(P,Q2), d_ref(P,Q3));
    } else {
        int s = (b - 1024) * 256 + threadIdx.x;   // < 4096
        float4 b0 = *(const float4*)(g_intra_b8 + s * 8);
        float4 b1 = *(const float4*)(g_intra_b8 + s * 8 + 4);
        float4 a0 = *(const float4*)(g_intra_a8 + s * 8);
        float4 a1 = *(const float4*)(g_intra_a8 + s * 8 + 4);
        int4 ab = g_anch_b[s];
        int4 aa = g_anch_a[s];
        float4 P0 = g_pts[ab.x], P1 = g_pts[ab.y], P2 = g_pts[ab.z], P3 = g_pts[ab.w];
        float4 Q0 = g_pts[si[aa.x]], Q1 = g_pts[si[aa.y]], Q2 = g_pts[si[aa.z]], Q3 = g_pts[si[aa.w]];
        float* o = g_adf + s * 28;
        ((float4*)o)[0] = make_float4(b0.x, b0.y, b0.z, b0.w);
        ((float4*)o)[1] = make_float4(b1.x, b1.y, a0.x, a0.y);
        ((float4*)o)[2] = make_float4(a0.z, a0.w, a1.x, a1.y);
        ((float4*)o)[3] = make_float4(d_ref(P0,Q0), d_ref(P0,Q1), d_ref(P0,Q2), d_ref(P0,Q3));
        ((float4*)o)[4] = make_float4(d_ref(P1,Q0), d_ref(P1,Q1), d_ref(P1,Q2), d_ref(P1,Q3));
        ((float4*)o)[5] = make_float4(d_ref(P2,Q0), d_ref(P2,Q1), d_ref(P2,Q2), d_ref(P2,Q3));
        ((float4*)o)[6] = make_float4(d_ref(P3,Q0), d_ref(P3,Q1), d_ref(P3,Q2), d_ref(P3,Q3));
    }
}

// ---------------- gemm1: y = adf @ {Ww|Wb} + {bw|bb}, thread per (s,ch) ----------------
__global__ void __launch_bounds__(256) gemm1_kernel(
    const float* __restrict__ Ww, const float* __restrict__ bw,
    const float* __restrict__ Wb, const float* __restrict__ bb) {
    int tid = blockIdx.x * blockDim.x + threadIdx.x;
    int ch = tid & 63, s = tid >> 6;
    float aw = bw[ch], ab = bb[ch];
    const float* a = g_adf + s * 28;
#pragma unroll
    for (int c = 0; c < 28; c++) {
        float av = a[c];
        aw = fmaf(av, Ww[c * 64 + ch], aw);
        ab = fmaf(av, Wb[c * 64 + ch], ab);
    }
    g_y[s * 128 + ch]      = aw;
    g_y[s * 128 + 64 + ch] = ab;
}

// ---------------- statspw1: BN stats (w & b) + gate + leaky, 2 channels/block ----------------
__global__ void __launch_bounds__(256) statspw1_kernel(
    const float* __restrict__ gw, const float* __restrict__ betaw,
    const float* __restrict__ gb, const float* __restrict__ betab,
    const float* __restrict__ feature, const int* __restrict__ si) {
    __shared__ float2 red[256], red2[256];
    __shared__ float  stats[8];
    int ch2 = blockIdx.x * 2, tid = threadIdx.x;
    float2 vw[16], vb[16];
    float2 sw = make_float2(0.f, 0.f), s2w = make_float2(0.f, 0.f);
    float2 sb = make_float2(0.f, 0.f), s2b = make_float2(0.f, 0.f);
#pragma unroll
    for (int i = 0; i < 16; i++) {
        int r = i * 256 + tid;
        float2 w = *(const float2*)(g_y + (size_t)r * 128 + ch2);
        float2 b = *(const float2*)(g_y + (size_t)r * 128 + 64 + ch2);
        vw[i] = w; vb[i] = b;
        sw.x += w.x; sw.y += w.y; s2w.x = fmaf(w.x, w.x, s2w.x); s2w.y = fmaf(w.y, w.y, s2w.y);
        sb.x += b.x; sb.y += b.y; s2b.x = fmaf(b.x, b.x, s2b.x); s2b.y = fmaf(b.y, b.y, s2b.y);
    }
    red[tid] = sw; red2[tid] = s2w; __syncthreads();
    for (int st = 128; st > 0; st >>= 1) {
        if (tid < st) {
            red[tid].x += red[tid + st].x;  red[tid].y += red[tid + st].y;
            red2[tid].x += red2[tid + st].x; red2[tid].y += red2[tid + st].y;
        }
        __syncthreads();
    }
    if (tid == 0) {
        float mu0 = red[0].x / (float)S_PTS, mu1 = red[0].y / (float)S_PTS;
        stats[0] = mu0; stats[1] = mu1;
        stats[2] = rsqrtf(red2[0].x / (float)S_PTS - mu0 * mu0 + 1e-5f);
        stats[3] = rsqrtf(red2[0].y / (float)S_PTS - mu1 * mu1 + 1e-5f);
    }
    __syncthreads();
    red[tid] = sb; red2[tid] = s2b; __syncthreads();
    for (int st = 128; st > 0; st >>= 1) {
        if (tid < st) {
            red[tid].x += red[tid + st].x;  red[tid].y += red[tid + st].y;
            red2[tid].x += red2[tid + st].x; red2[tid].y += red2[tid + st].y;
        }
        __syncthreads();
    }
    if (tid == 0) {
        float mu0 = red[0].x / (float)S_PTS, mu1 = red[0].y / (float)S_PTS;
        stats[4] = mu0; stats[5] = mu1;
        stats[6] = rsqrtf(red2[0].x / (float)S_PTS - mu0 * mu0 + 1e-5f);
        stats[7] = rsqrtf(red2[0].y / (float)S_PTS - mu1 * mu1 + 1e-5f);
    }
    __syncthreads();
    float muw0 = stats[0], muw1 = stats[1], rsw0 = stats[2], rsw1 = stats[3];
    float mub0 = stats[4], mub1 = stats[5], rsb0 = stats[6], rsb1 = stats[7];
    float gw0 = gw[ch2], gw1 = gw[ch2 + 1], bew0 = betaw[ch2], bew1 = betaw[ch2 + 1];
    float gb0 = gb[ch2], gb1 = gb[ch2 + 1], beb0 = betab[ch2], beb1 = betab[ch2 + 1];
#pragma unroll
    for (int i = 0; i < 16; i++) {
        int r = i * 256 + tid;
        float2 f = *(const float2*)(feature + (size_t)si[r] * 64 + ch2);
        float w0 = (vw[i].x - muw0) * rsw0 * gw0 + bew0;
        float w1 = (vw[i].y - muw1) * rsw1 * gw1 + bew1;
        float b0 = (vb[i].x - mub0) * rsb0 * gb0 + beb0;
        float b1 = (vb[i].y - mub1) * rsb1 * gb1 + beb1;
        g_fmT[(size_t)ch2 * S_PTS + r]       = leaky(fmaf(f.x, w0, b0));
        g_fmT[(size_t)(ch2 + 1) * S_PTS + r] = leaky(fmaf(f.y, w1, b1));
    }
}

// ---------------- GEMM2: z = [fm | adf] @ Wo + bo, 4 channels/thread, float4 Wo ----------------
// fma order per channel identical to the 1-ch version -> bitwise-identical z.
__global__ void __launch_bounds__(256) gemm2_kernel(const float* __restrict__ Wo,
                                                    const float* __restrict__ bo) {
    int tid = blockIdx.x * blockDim.x + threadIdx.x;    // < S_PTS*32
    int ch = (tid & 31) * 4, s = tid >> 5;
    float4 acc = *(const float4*)(bo + ch);
#pragma unroll
    for (int c = 0; c < 64; c++) {
        float f = g_fmT[c * S_PTS + s];
        float4 w = *(const float4*)(Wo + c * 128 + ch);
        acc.x = fmaf(f, w.x, acc.x);
        acc.y = fmaf(f, w.y, acc.y);
        acc.z = fmaf(f, w.z, acc.z);
        acc.w = fmaf(f, w.w, acc.w);
    }
    const float* a = g_adf + s * 28;
#pragma unroll
    for (int c = 0; c < 28; c++) {
        float av = a[c];
        float4 w = *(const float4*)(Wo + (64 + c) * 128 + ch);
        acc.x = fmaf(av, w.x, acc.x);
        acc.y = fmaf(av, w.y, acc.y);
        acc.z = fmaf(av, w.z, acc.z);
        acc.w = fmaf(av, w.w, acc.w);
    }
    *(float4*)(g_z + (size_t)s * 128 + ch) = acc;
}

// ---------------- bnpw2: BN stats + affine + leaky, 4 channels/block, float4 I/O ----------------
__global__ void __launch_bounds__(256) bnpw2_kernel(const float* __restrict__ go,
                                                    const float* __restrict__ betao,
                                                    float* __restrict__ out_feat) {
    __shared__ float4 red[256], red2[256];
    __shared__ float4 stats[2];
    int ch4 = blockIdx.x * 4, tid = threadIdx.x;
    float4 v[16];
    float4 s  = make_float4(0.f, 0.f, 0.f, 0.f);
    float4 s2 = make_float4(0.f, 0.f, 0.f, 0.f);
#pragma unroll
    for (int i = 0; i < 16; i++) {
        int r = i * 256 + tid;
        float4 val = *(const float4*)(g_z + (size_t)r * 128 + ch4);
        v[i] = val;
        s.x += val.x; s.y += val.y; s.z += val.z; s.w += val.w;
        s2.x = fmaf(val.x, val.x, s2.x); s2.y = fmaf(val.y, val.y, s2.y);
        s2.z = fmaf(val.z, val.z, s2.z); s2.w = fmaf(val.w, val.w, s2.w);
    }
    red[tid] = s; red2[tid] = s2;
    __syncthreads();
    for (int st = 128; st > 0; st >>= 1) {
        if (tid < st) {
            float4 a = red[tid + st], a2 = red2[tid + st];
            red[tid].x += a.x; red[tid].y += a.y; red[tid].z += a.z; red[tid].w += a.w;
            red2[tid].x += a2.x; red2[tid].y += a2.y; red2[tid].z += a2.z; red2[tid].w += a2.w;
        }
        __syncthreads();
    }
    if (tid == 0) {
        float4 sum = red[0], sum2 = red2[0];
        float4 mu = make_float4(sum.x / S_PTS, sum.y / S_PTS, sum.z / S_PTS, sum.w / S_PTS);
        stats[0] = mu;
        stats[1] = make_float4(rsqrtf(sum2.x / S_PTS - mu.x * mu.x + 1e-5f),
                               rsqrtf(sum2.y / S_PTS - mu.y * mu.y + 1e-5f),
                               rsqrtf(sum2.z / S_PTS - mu.z * mu.z + 1e-5f),
                               rsqrtf(sum2.w / S_PTS - mu.w * mu.w + 1e-5f));
    }
    __syncthreads();
    float4 mu = stats[0], rs = stats[1];
    float4 g  = *(const float4*)(go + ch4);
    float4 be = *(const float4*)(betao + ch4);
#pragma unroll
    for (int i = 0; i < 16; i++) {
        int r = i * 256 + tid;
        float4 val = v[i];
        float4 o;
        o.x = leaky((val.x - mu.x) * rs.x * g.x + be.x);
        o.y = leaky((val.y - mu.y) * rs.y * g.y + be.y);
        o.z = leaky((val.z - mu.z) * rs.z * g.z + be.z);
        o.w = leaky((val.w - mu.w) * rs.w * g.w + be.w);
        *(float4*)(out_feat + (size_t)r * 128 + ch4) = o;
    }
}

// ---------------- launch ----------------
extern "C" void kernel_launch(void* const* d_in, const int* in_sizes, int n_in,
                              void* d_out, int out_size) {
    const float* xyz     = (const float*)d_in[0];
    const float* feature = (const float*)d_in[1];
    const int*   si      = (const int*)  d_in[2];
    const float* Ww    = (const float*)d_in[3];
    const float* bw    = (const float*)d_in[4];
    const float* gw    = (const float*)d_in[5];
    const float* betaw = (const float*)d_in[6];
    const float* Wb    = (const float*)d_in[7];
    const float* bb    = (const float*)d_in[8];
    const float* gb    = (const float*)d_in[9];
    const float* betab = (const float*)d_in[10];
    const float* Wo    = (const float*)d_in[11];
    const float* bo    = (const float*)d_in[12];
    const float* go    = (const float*)d_in[13];
    const float* betao = (const float*)d_in[14];

    float* out        = (float*)d_out;
    float* out_xyz_s  = out;                                  // 4096*3
    float* out_feat   = out + S_PTS * 3;                      // 4096*128
    float* out_rf     = out_feat + S_PTS * 128;               // 4096*16*28
    float* out_ni     = out_rf + (size_t)S_PTS * KNN * 28;    // 4096*16

    prep_kernel<<<(N_PTS + 255) / 256, 256>>>(xyz, si, out_xyz_s);
    scan_kernel<<<1, 1024>>>();
    scatter_kernel<<<(N_PTS + S_PTS) / 256, 256>>>();
    knn_kernel<<<1024, 256>>>(out_ni);                         // 8192 warps
    rf_adf_kernel<<<1040, 256>>>(out_rf, si);
    gemm1_kernel<<<(S_PTS * 64) / 256, 256>>>(Ww, bw, Wb, bb);
    statspw1_kernel<<<32, 256>>>(gw, betaw, gb, betab, feature, si);
    gemm2_kernel<<<(S_PTS * 32) / 256, 256>>>(Wo, bo);
    bnpw2_kernel<<<32, 256>>>(go, betao, out_feat);
}